// round 15
// baseline (speedup 1.0000x reference)
#include <cuda_runtime.h>
#include <cuda_fp16.h>
#include <cstdint>

#define B_   128
#define T_   512
#define E_   512
#define H_   1024
#define G3H_ 3072
#define NROW 65536   // B*T

#define NCTA 128     // CTAs in persistent recurrence
#define COLS 8       // h-columns per CTA
#define THR  512     // 16 warps: 8 M-slices x 2 K-halves
#define NKT  8       // stages per K-half (512/64)

// ---- recurrence SMEM layout (bytes) ----
#define WP_OFF   0                       // packed fp16 weights: 6144 entries x 8B = 48KB
#define AS_OFF   49152                   // 16 warps x 3 stages x 2304B = 108KB
#define ASTG     2304                    // stage: 16 rows x (128B data + 16B pad)
#define AWARP    (3 * ASTG)
#define GX_OFF   159744                  // 2 buffers x 128 rows x 64B (24 fp16 + pad)
#define GX_ROWB  64
#define GX_BUF   8192
#define HOLD_OFF 176128                  // 128 rows x 16B (8 fp16), persistent
#define BIAS_OFF 178176                  // 24 fp32 (+pad)
#define SCR_OFF  178304                  // 256 threads x 12 fp32 partials
#define REC_SMEM (SCR_OFF + 12288)       // 190592

// gemm: 3 stages x (A 256 rows + W 128 rows) x 20 words
#define GSTG_W   7680                    // words per stage (A 5120 + W 2560)
#define GEMM_SMEM (3 * GSTG_W * 4)       // 92160 B

// ---------------- device scratch ----------------
__device__ __half g_x0 [(size_t)NROW * E_];
__device__ __half g_y0 [(size_t)NROW * H_];
__device__ __half g_gx0[(size_t)NROW * G3H_];
__device__ __half g_gx1[(size_t)NROW * G3H_];
__device__ __half g_wih0[G3H_ * E_];
__device__ __half g_wih1[G3H_ * H_];
__device__ __half g_h0[2][B_ * H_];
__device__ __half g_h1[2][B_ * H_];
__device__ unsigned g_flags0[NCTA * 32];
__device__ unsigned g_flags1[NCTA * 32];

// ---------------- helpers ----------------
__device__ __forceinline__ void cp16(void* s, const void* g) {
    uint32_t sa = (uint32_t)__cvta_generic_to_shared(s);
    asm volatile("cp.async.cg.shared.global [%0], [%1], 16;" :: "r"(sa), "l"(g));
}
__device__ __forceinline__ void cpcommit() { asm volatile("cp.async.commit_group;"); }

__device__ __forceinline__ void mma16(float c[4], const uint32_t a[4], const uint32_t b[2]) {
    asm volatile(
        "mma.sync.aligned.m16n8k16.row.col.f32.f16.f16.f32 "
        "{%0,%1,%2,%3}, {%4,%5,%6,%7}, {%8,%9}, {%0,%1,%2,%3};"
        : "+f"(c[0]), "+f"(c[1]), "+f"(c[2]), "+f"(c[3])
        : "r"(a[0]), "r"(a[1]), "r"(a[2]), "r"(a[3]), "r"(b[0]), "r"(b[1]));
}

__device__ __forceinline__ void ldsm4(uint32_t a[4], uint32_t addr) {
    asm volatile("ldmatrix.sync.aligned.m8n8.x4.shared.b16 {%0,%1,%2,%3}, [%4];"
                 : "=r"(a[0]), "=r"(a[1]), "=r"(a[2]), "=r"(a[3]) : "r"(addr));
}

__device__ __forceinline__ float tanh_ap(float x) {
    float y;
    asm("tanh.approx.f32 %0, %1;" : "=f"(y) : "f"(x));
    return y;
}
__device__ __forceinline__ float sigm_ap(float x) {
    return 0.5f + 0.5f * tanh_ap(0.5f * x);
}

// wait for 8 producer CTAs (lanes 0-7 poll one flag each)
__device__ __forceinline__ void wait_prod(const unsigned* flags, int base, int lane,
                                          unsigned tgt) {
    unsigned ok;
    do {
        ok = 1u;
        if (lane < 8) {
            unsigned v;
            asm volatile("ld.acquire.gpu.global.u32 %0, [%1];"
                         : "=r"(v) : "l"(flags + (base + lane) * 32) : "memory");
            ok = (v >= tgt) ? 1u : 0u;
        }
    } while (__all_sync(0xffffffffu, ok) == 0);
}

// fused wait for stages 0+1 producers (lanes 0-15 poll one flag each)
__device__ __forceinline__ void wait_prod01(const unsigned* flags, int base, int lane,
                                            unsigned tgt) {
    unsigned ok;
    do {
        ok = 1u;
        if (lane < 16) {
            unsigned v;
            asm volatile("ld.acquire.gpu.global.u32 %0, [%1];"
                         : "=r"(v) : "l"(flags + (base + lane) * 32) : "memory");
            ok = (v >= tgt) ? 1u : 0u;
        }
    } while (__all_sync(0xffffffffu, ok) == 0);
}

// ---------------- setup: fp16-convert wih, zero h, reset flags ----------------
__global__ void k_setup(const float* __restrict__ wih0, const float* __restrict__ wih1) {
    int stride = gridDim.x * blockDim.x;
    for (int i = blockIdx.x * blockDim.x + threadIdx.x; i < G3H_ * H_; i += stride) {
        if (i < G3H_ * E_) g_wih0[i] = __float2half_rn(wih0[i]);
        g_wih1[i] = __float2half_rn(wih1[i]);
        if (i < 2 * B_ * H_) {
            (&g_h0[0][0])[i] = __float2half_rn(0.f);
            (&g_h1[0][0])[i] = __float2half_rn(0.f);
        }
        if (i < NCTA * 32) { g_flags0[i] = 0u; g_flags1[i] = 0u; }
    }
}

__global__ void k_gather(const int* __restrict__ src, const float* __restrict__ emb,
                         __half* __restrict__ x0) {
    int row = blockIdx.x;
    int v = src[row];
    const float* e = emb + (size_t)v * E_;
    __half* o = x0 + (size_t)row * E_;
    for (int j = threadIdx.x; j < E_; j += blockDim.x) o[j] = __float2half_rn(e[j]);
}

// ---------------- big GEMM (fp16 m16n8k16, 256x128 tile, 512 thr): C = A*W^T + bias (fp16 out) ----------------
__device__ __forceinline__ void gemm_load(uint32_t* stg, const __half* Ab, const __half* Wb,
                                          int K, int kt, int tid) {
    #pragma unroll
    for (int i = 0; i < 3; i++) {
        int id = tid + 512 * i;
        if (id < 1024) {                         // A: 256 rows x 4 chunks
            int r = id >> 2, s = id & 3;
            cp16(stg + r * 20 + s * 4, Ab + (size_t)r * K + kt * 32 + s * 8);
        } else {                                 // W: 128 rows x 4 chunks
            int j = id - 1024;
            int r = j >> 2, s = j & 3;
            cp16(stg + 5120 + r * 20 + s * 4, Wb + (size_t)r * K + kt * 32 + s * 8);
        }
    }
    cpcommit();
}

__global__ __launch_bounds__(512) void k_gemm(const __half* __restrict__ A,
                                              const __half* __restrict__ W,
                                              const float* __restrict__ bias,
                                              __half* __restrict__ C, int K) {
    extern __shared__ uint32_t gsm[];
    int tid = threadIdx.x;
    int lane = tid & 31, wid = tid >> 5;
    int g = lane >> 2, tg = lane & 3;
    int wM = wid & 3, wN = wid >> 2;            // 4 warps M (64 rows), 4 warps N (32 cols)
    const __half* Ab = A + (size_t)blockIdx.y * 256 * K;
    const __half* Wb = W + (size_t)blockIdx.x * 128 * K;

    float c[4][4][4];
    #pragma unroll
    for (int i = 0; i < 4; i++)
        #pragma unroll
        for (int j = 0; j < 4; j++)
            #pragma unroll
            for (int e = 0; e < 4; e++) c[i][j][e] = 0.f;

    int KIT = K / 32;
    gemm_load(gsm, Ab, Wb, K, 0, tid);
    gemm_load(gsm + GSTG_W, Ab, Wb, K, 1, tid);

    for (int kt = 0; kt < KIT; kt++) {
        asm volatile("cp.async.wait_group 1;");
        __syncthreads();
        if (kt + 2 < KIT) gemm_load(gsm + ((kt + 2) % 3) * GSTG_W, Ab, Wb, K, kt + 2, tid);
        else cpcommit();
        uint32_t* As = gsm + (kt % 3) * GSTG_W;
        uint32_t* Ws = As + 5120;
        #pragma unroll
        for (int ch = 0; ch < 2; ch++) {
            int co = ch * 8;
            uint32_t a[4][4], b[4][2];
            #pragma unroll
            for (int mt = 0; mt < 4; mt++) {
                int r0 = wM * 64 + mt * 16 + g;
                a[mt][0] = As[r0 * 20 + co + tg];
                a[mt][1] = As[(r0 + 8) * 20 + co + tg];
                a[mt][2] = As[r0 * 20 + co + tg + 4];
                a[mt][3] = As[(r0 + 8) * 20 + co + tg + 4];
            }
            #pragma unroll
            for (int nt = 0; nt < 4; nt++) {
                int n0 = wN * 32 + nt * 8 + g;
                b[nt][0] = Ws[n0 * 20 + co + tg];
                b[nt][1] = Ws[n0 * 20 + co + tg + 4];
            }
            #pragma unroll
            for (int mt = 0; mt < 4; mt++)
                #pragma unroll
                for (int nt = 0; nt < 4; nt++) mma16(c[mt][nt], a[mt], b[nt]);
        }
        // no bottom sync: 3-stage ring + wait_group 1 keeps writers/readers disjoint
    }

    size_t row0 = (size_t)blockIdx.y * 256;
    int col0 = blockIdx.x * 128 + wN * 32;
    #pragma unroll
    for (int mt = 0; mt < 4; mt++)
        #pragma unroll
        for (int nt = 0; nt < 4; nt++)
            #pragma unroll
            for (int ep = 0; ep < 2; ep++) {
                size_t row = row0 + wM * 64 + mt * 16 + g + ep * 8;
                int col = col0 + nt * 8 + 2 * tg;
                float vx = c[mt][nt][2 * ep]     + bias[col];
                float vy = c[mt][nt][2 * ep + 1] + bias[col + 1];
                *(__half2*)&C[row * G3H_ + col] = __floats2half2_rn(vx, vy);
            }
}

// ---------------- persistent recurrence: 128 CTAs x 8 cols, dataflow-pipelined ----------------
__global__ __launch_bounds__(THR, 1) void k_rec_persist(
    const float* __restrict__ W,      // whh raw fp32 [3072][1024]
    const __half* __restrict__ gx,    // [B][T][3H] fp16
    const float* __restrict__ bhh,    // [3H]
    __half* __restrict__ hbuf,        // [2][B*H] ping-pong fp16
    __half* __restrict__ yout,        // [B][T][H] fp16 or nullptr
    float* __restrict__ outf,         // [B][H] final hidden fp32
    unsigned* __restrict__ flags) {
    extern __shared__ char smc[];
    uint32_t* Wp  = (uint32_t*)(smc + WP_OFF);
    __half*   hds = (__half*)(smc + HOLD_OFF);
    float*    bhs = (float*)(smc + BIAS_OFF);
    float*    scr = (float*)(smc + SCR_OFF);

    int tid = threadIdx.x;
    int lane = tid & 31, wid = tid >> 5;
    int g = lane >> 2, tg = lane & 3;
    int wM = wid & 7;                  // batch slice (16 rows)
    int kh = wid >> 3;                 // K half
    int bid = blockIdx.x;
    int nb = bid * COLS;
    int pbase = kh * 64;               // producer-CTA base for this K half

    // pack resident weights: entry e = (k16*3+gt)*32+lane -> 2 words
    for (int e = tid; e < 6144; e += THR) {
        int lane_ = e & 31;
        int r = e >> 5;
        int gt = r % 3;
        int k16 = r / 3;
        int n = gt * H_ + nb + (lane_ >> 2);
        int k = k16 * 16 + 2 * (lane_ & 3);
        const float* wr = W + (size_t)n * H_;
        __half2 w0 = __floats2half2_rn(wr[k],     wr[k + 1]);
        __half2 w1 = __floats2half2_rn(wr[k + 8], wr[k + 9]);
        Wp[e * 2]     = *(uint32_t*)&w0;
        Wp[e * 2 + 1] = *(uint32_t*)&w1;
    }
    if (tid < 24) bhs[tid] = bhh[(tid >> 3) * H_ + nb + (tid & 7)];
    ((uint32_t*)hds)[tid] = 0u;    // persistent holds = h(0) = 0 (512 words)
    __syncthreads();

    char* myA = smc + AS_OFF + wid * AWARP;
    uint32_t aLdsm = (uint32_t)__cvta_generic_to_shared(myA)
                   + (uint32_t)(lane & 15) * 144 + (uint32_t)(lane >> 4) * 16;

    // per-thread stage-load map: 4 chunks of 16B (16 rows x 128B per stage)
    int srcOff[4]; int dstOff[4];
    #pragma unroll
    for (int i = 0; i < 4; i++) {
        int ch = lane + 32 * i;
        int r = ch >> 3, cc = ch & 7;
        srcOff[i] = r * H_ + kh * 512 + cc * 8;     // fp16 elements
        dstOff[i] = r * 144 + cc * 16;              // bytes within stage
    }

    // gx tile: 128 rows x 3 chunks (16B = 8 fp16 = one gate's 8 cols)
    // preload gx(0) into buffer 0 (kh==1 threads only; own commit group)
    if (kh == 1) {
        #pragma unroll
        for (int i = 0; i < 2; i++) {
            int idx = (tid - 256) + 256 * i;
            if (idx < 384) {
                int row = idx / 3, part = idx % 3;
                cp16(smc + GX_OFF + row * GX_ROWB + part * 16,
                     gx + (size_t)row * (T_ * G3H_) + (size_t)part * H_ + nb);
            }
        }
        cpcommit();
    }

    for (int t = 0; t < T_; t++) {
        const __half* hin = hbuf + (size_t)(t & 1) * (B_ * H_);
        __half* hout = hbuf + (size_t)((t + 1) & 1) * (B_ * H_);
        const __half* hwarp = hin + (size_t)(wM * 16) * H_;
        const __half* gxs = (const __half*)(smc + GX_OFF + (t & 1) * GX_BUF);
        unsigned tgt = (unsigned)t;

        float c[3][4];
        #pragma unroll
        for (int j = 0; j < 3; j++)
            #pragma unroll
            for (int e = 0; e < 4; e++) c[j][e] = 0.f;

        // wait for producers of stages 0+1, then load them (one group each)
        wait_prod01(flags, pbase, lane, tgt);
        #pragma unroll
        for (int s = 0; s < 2; s++) {
            char* dst = myA + s * ASTG;
            const __half* hsrc = hwarp + s * 64;
            #pragma unroll
            for (int i = 0; i < 4; i++)
                cp16(dst + dstOff[i], hsrc + srcOff[i]);
            cpcommit();
        }

        for (int kt = 0; kt < NKT; kt++) {
            asm volatile("cp.async.wait_group 1;");

            uint32_t stAddr = aLdsm + (uint32_t)((kt % 3) * ASTG);
            #pragma unroll
            for (int c16 = 0; c16 < 4; c16++) {
                uint32_t a[4];
                ldsm4(a, stAddr + (uint32_t)c16 * 32);
                int k16 = kh * 32 + kt * 4 + c16;
                #pragma unroll
                for (int gt = 0; gt < 3; gt++) {
                    uint2 bv = *(const uint2*)&Wp[((k16 * 3 + gt) * 32 + lane) * 2];
                    uint32_t b[2] = { bv.x, bv.y };
                    mma16(c[gt], a, b);
                }
            }

            // prefetch stage kt+2 after this stage's MMAs (producer wait off compute path)
            if (kt + 2 < NKT) {
                wait_prod(flags, pbase + (kt + 2) * 8, lane, tgt);
                char* dst = myA + ((kt + 2) % 3) * ASTG;
                const __half* hsrc = hwarp + (kt + 2) * 64;
                #pragma unroll
                for (int i = 0; i < 4; i++)
                    cp16(dst + dstOff[i], hsrc + srcOff[i]);
            }
            cpcommit();
        }

        // drain; kh==1 writes partials + prefetches gx(t+1); one bar; kh==0 epilogue
        asm volatile("cp.async.wait_group 0;");
        if (kh == 1) {
            float4* s = (float4*)(scr + ((size_t)(wid - 8) * 32 + lane) * 12);
            s[0] = make_float4(c[0][0], c[0][1], c[0][2], c[0][3]);
            s[1] = make_float4(c[1][0], c[1][1], c[1][2], c[1][3]);
            s[2] = make_float4(c[2][0], c[2][1], c[2][2], c[2][3]);
            if (t + 1 < T_) {
                char* gdst = smc + GX_OFF + ((t + 1) & 1) * GX_BUF;
                #pragma unroll
                for (int i = 0; i < 2; i++) {
                    int idx = (tid - 256) + 256 * i;
                    if (idx < 384) {
                        int row = idx / 3, part = idx % 3;
                        cp16(gdst + row * GX_ROWB + part * 16,
                             gx + (size_t)row * (T_ * G3H_) + (size_t)(t + 1) * G3H_
                                + (size_t)part * H_ + nb);
                    }
                }
                cpcommit();
            }
        }
        __syncthreads();

        if (kh == 0) {
            const float4* s = (const float4*)(scr + ((size_t)wid * 32 + lane) * 12);
            float4 p0 = s[0], p1 = s[1], p2 = s[2];
            c[0][0] += p0.x; c[0][1] += p0.y; c[0][2] += p0.z; c[0][3] += p0.w;
            c[1][0] += p1.x; c[1][1] += p1.y; c[1][2] += p1.z; c[1][3] += p1.w;
            c[2][0] += p2.x; c[2][1] += p2.y; c[2][2] += p2.z; c[2][3] += p2.w;

            #pragma unroll
            for (int ep = 0; ep < 2; ep++) {
                int row = wM * 16 + g + ep * 8;
                const __half* gxr = gxs + row * 32;      // 32 halves per row (24 + pad)
                __half* hrow_s = hds + row * 8;
                float2 hv;
                #pragma unroll
                for (int hf = 0; hf < 2; hf++) {
                    int e = 2 * ep + hf;
                    int lc = 2 * tg + hf;
                    float xr = __half2float(gxr[lc]);
                    float xz = __half2float(gxr[8 + lc]);
                    float xn = __half2float(gxr[16 + lc]);
                    float hr = c[0][e] + bhs[lc];
                    float hz = c[1][e] + bhs[8 + lc];
                    float hn = c[2][e] + bhs[16 + lc];
                    float rr = sigm_ap(xr + hr);
                    float zz = sigm_ap(xz + hz);
                    float nn = tanh_ap(xn + rr * hn);
                    float ho = __half2float(hrow_s[lc]);
                    float hnew = (1.f - zz) * nn + zz * ho;
                    (hf ? hv.y : hv.x) = hnew;
                }
                int col = nb + 2 * tg;
                __half2 hq = __floats2half2_rn(hv.x, hv.y);
                *(__half2*)&hrow_s[2 * tg] = hq;                 // persistent h_old
                *(__half2*)&hout[(size_t)row * H_ + col] = hq;
                if (yout)
                    *(__half2*)&yout[(size_t)row * (T_ * H_) + (size_t)t * H_ + col] = hq;
                if (t == T_ - 1) *(float2*)&outf[(size_t)row * H_ + col] = hv;
            }
        }

        // publish this CTA's h(t+1) columns (after epilogue stores are CTA-visible)
        __syncthreads();
        if (tid == 0 && t + 1 < T_)
            asm volatile("st.release.gpu.global.u32 [%0], %1;"
                         :: "l"(flags + bid * 32), "r"((unsigned)(t + 1)) : "memory");
    }
}

// ---------------- launch ----------------
extern "C" void kernel_launch(void* const* d_in, const int* in_sizes, int n_in,
                              void* d_out, int out_size) {
    const int*   src  = (const int*)d_in[0];
    const float* emb  = (const float*)d_in[1];
    const float* wih0 = (const float*)d_in[2];
    const float* whh0 = (const float*)d_in[3];
    const float* bih0 = (const float*)d_in[4];
    const float* bhh0 = (const float*)d_in[5];
    const float* wih1 = (const float*)d_in[6];
    const float* whh1 = (const float*)d_in[7];
    const float* bih1 = (const float*)d_in[8];
    const float* bhh1 = (const float*)d_in[9];
    float* out = (float*)d_out;

    __half *x0, *y0, *gx0, *gx1, *pwih0, *pwih1, *h0, *h1;
    unsigned *fl0, *fl1;
    cudaGetSymbolAddress((void**)&x0,    g_x0);
    cudaGetSymbolAddress((void**)&y0,    g_y0);
    cudaGetSymbolAddress((void**)&gx0,   g_gx0);
    cudaGetSymbolAddress((void**)&gx1,   g_gx1);
    cudaGetSymbolAddress((void**)&pwih0, g_wih0);
    cudaGetSymbolAddress((void**)&pwih1, g_wih1);
    cudaGetSymbolAddress((void**)&h0,    g_h0);
    cudaGetSymbolAddress((void**)&h1,    g_h1);
    cudaGetSymbolAddress((void**)&fl0,   g_flags0);
    cudaGetSymbolAddress((void**)&fl1,   g_flags1);

    cudaFuncSetAttribute(k_rec_persist, cudaFuncAttributeMaxDynamicSharedMemorySize, REC_SMEM);
    cudaFuncSetAttribute(k_gemm, cudaFuncAttributeMaxDynamicSharedMemorySize, GEMM_SMEM);

    // launch order keeps k_rec_persist at my-launch-index 3 for the ncu -s 5 window
    k_setup<<<2048, 256>>>(wih0, wih1);                                   // 0
    k_gather<<<NROW, 128>>>(src, emb, x0);                                // 1
    k_gemm<<<dim3(24, 256), 512, GEMM_SMEM>>>(x0, pwih0, bih0, gx0, E_);  // 2
    k_rec_persist<<<NCTA, THR, REC_SMEM>>>(whh0, gx0, bhh0, h0, y0, out, fl0);        // 3
    k_gemm<<<dim3(24, 256), 512, GEMM_SMEM>>>(y0, pwih1, bih1, gx1, H_);  // 4
    k_rec_persist<<<NCTA, THR, REC_SMEM>>>(whh1, gx1, bhh1, h1, nullptr, out + B_ * H_, fl1); // 5
}

// round 16
// speedup vs baseline: 1.1994x; 1.1994x over previous
#include <cuda_runtime.h>
#include <cuda_fp16.h>
#include <cstdint>

#define B_   128
#define T_   512
#define E_   512
#define H_   1024
#define G3H_ 3072
#define NROW 65536   // B*T

#define NCTA 128     // CTAs in persistent recurrence
#define COLS 8       // h-columns per CTA
#define THR  512     // 16 warps: 8 M-slices x 2 K-halves
#define NKT  8       // stages per K-half (512/64)

// ---- recurrence SMEM layout (bytes) ----
#define WP_OFF   0                       // packed fp16 weights: 6144 entries x 8B = 48KB
#define AS_OFF   49152                   // 16 warps x 3 stages x 2304B = 108KB
#define ASTG     2304                    // stage: 16 rows x (128B data + 16B pad)
#define AWARP    (3 * ASTG)
#define GX_OFF   159744                  // 2 buffers x 128 rows x 64B (24 fp16 + pad)
#define GX_ROWB  64
#define GX_BUF   8192
#define HOLD_OFF 176128                  // 128 rows x 16B (8 fp16), persistent
#define BIAS_OFF 178176                  // 24 fp32 (+pad)
#define SCR_OFF  178304                  // 256 threads x 12 fp32 partials
#define REC_SMEM (SCR_OFF + 12288)       // 190592

// gemm: 3 stages x (A 256 rows + W 128 rows) x 20 words
#define GSTG_W   7680                    // words per stage (A 5120 + W 2560)
#define GSTG_B   30720                   // bytes per stage
#define GEMM_SMEM (3 * GSTG_B)           // 92160 B

// ---------------- device scratch ----------------
__device__ __half g_x0 [(size_t)NROW * E_];
__device__ __half g_y0 [(size_t)NROW * H_];
__device__ __half g_gx0[(size_t)NROW * G3H_];
__device__ __half g_gx1[(size_t)NROW * G3H_];
__device__ __half g_wih0[G3H_ * E_];
__device__ __half g_wih1[G3H_ * H_];
__device__ __half g_h0[2][B_ * H_];
__device__ __half g_h1[2][B_ * H_];
__device__ unsigned g_flags0[NCTA * 32];
__device__ unsigned g_flags1[NCTA * 32];

// ---------------- helpers ----------------
__device__ __forceinline__ void cp16(void* s, const void* g) {
    uint32_t sa = (uint32_t)__cvta_generic_to_shared(s);
    asm volatile("cp.async.cg.shared.global [%0], [%1], 16;" :: "r"(sa), "l"(g));
}
__device__ __forceinline__ void cpcommit() { asm volatile("cp.async.commit_group;"); }

__device__ __forceinline__ void mma16(float c[4], const uint32_t a[4], const uint32_t b[2]) {
    asm volatile(
        "mma.sync.aligned.m16n8k16.row.col.f32.f16.f16.f32 "
        "{%0,%1,%2,%3}, {%4,%5,%6,%7}, {%8,%9}, {%0,%1,%2,%3};"
        : "+f"(c[0]), "+f"(c[1]), "+f"(c[2]), "+f"(c[3])
        : "r"(a[0]), "r"(a[1]), "r"(a[2]), "r"(a[3]), "r"(b[0]), "r"(b[1]));
}

__device__ __forceinline__ void ldsm4(uint32_t a[4], uint32_t addr) {
    asm volatile("ldmatrix.sync.aligned.m8n8.x4.shared.b16 {%0,%1,%2,%3}, [%4];"
                 : "=r"(a[0]), "=r"(a[1]), "=r"(a[2]), "=r"(a[3]) : "r"(addr));
}

__device__ __forceinline__ float tanh_ap(float x) {
    float y;
    asm("tanh.approx.f32 %0, %1;" : "=f"(y) : "f"(x));
    return y;
}
__device__ __forceinline__ float sigm_ap(float x) {
    return 0.5f + 0.5f * tanh_ap(0.5f * x);
}

// parallel-poll grid barrier: 1 writer, NCTA pollers (one flag each)
__device__ __forceinline__ void flag_barrier(unsigned* flags, int bid, int tid,
                                             unsigned target) {
    __syncthreads();
    if (tid == 0)
        asm volatile("st.release.gpu.global.u32 [%0], %1;"
                     :: "l"(flags + bid * 32), "r"(target) : "memory");
    if (tid < NCTA) {
        unsigned v;
        do {
            asm volatile("ld.acquire.gpu.global.u32 %0, [%1];"
                         : "=r"(v) : "l"(flags + tid * 32) : "memory");
        } while (v < target);
    }
    __syncthreads();
}

// ---------------- setup: fp16-convert wih, zero h, reset flags ----------------
__global__ void k_setup(const float* __restrict__ wih0, const float* __restrict__ wih1) {
    int stride = gridDim.x * blockDim.x;
    for (int i = blockIdx.x * blockDim.x + threadIdx.x; i < G3H_ * H_; i += stride) {
        if (i < G3H_ * E_) g_wih0[i] = __float2half_rn(wih0[i]);
        g_wih1[i] = __float2half_rn(wih1[i]);
        if (i < 2 * B_ * H_) {
            (&g_h0[0][0])[i] = __float2half_rn(0.f);
            (&g_h1[0][0])[i] = __float2half_rn(0.f);
        }
        if (i < NCTA * 32) { g_flags0[i] = 0u; g_flags1[i] = 0u; }
    }
}

__global__ void k_gather(const int* __restrict__ src, const float* __restrict__ emb,
                         __half* __restrict__ x0) {
    int row = blockIdx.x;
    int v = src[row];
    const float* e = emb + (size_t)v * E_;
    __half* o = x0 + (size_t)row * E_;
    for (int j = threadIdx.x; j < E_; j += blockDim.x) o[j] = __float2half_rn(e[j]);
}

// ---------------- big GEMM (fp16 m16n8k16 + ldmatrix, 256x128 tile, 512 thr) ----------------
__device__ __forceinline__ void gemm_load(uint32_t* stg, const __half* Ab, const __half* Wb,
                                          int K, int kt, int tid) {
    #pragma unroll
    for (int i = 0; i < 3; i++) {
        int id = tid + 512 * i;
        if (id < 1024) {                         // A: 256 rows x 4 chunks
            int r = id >> 2, s = id & 3;
            cp16(stg + r * 20 + s * 4, Ab + (size_t)r * K + kt * 32 + s * 8);
        } else {                                 // W: 128 rows x 4 chunks
            int j = id - 1024;
            int r = j >> 2, s = j & 3;
            cp16(stg + 5120 + r * 20 + s * 4, Wb + (size_t)r * K + kt * 32 + s * 8);
        }
    }
    cpcommit();
}

__global__ __launch_bounds__(512) void k_gemm(const __half* __restrict__ A,
                                              const __half* __restrict__ W,
                                              const float* __restrict__ bias,
                                              __half* __restrict__ C, int K) {
    extern __shared__ uint32_t gsm[];
    int tid = threadIdx.x;
    int lane = tid & 31, wid = tid >> 5;
    int g = lane >> 2, tg = lane & 3;
    int wM = wid & 3, wN = wid >> 2;            // 4 warps M (64 rows), 4 warps N (32 cols)
    const __half* Ab = A + (size_t)blockIdx.y * 256 * K;
    const __half* Wb = W + (size_t)blockIdx.x * 128 * K;

    uint32_t smemB = (uint32_t)__cvta_generic_to_shared(gsm);
    // ldmatrix bases (stage/mt/ch offsets added at use)
    // A: lanes 0-7 rows+0..7 kLo | 8-15 rows+8..15 kLo | 16-23 rows+0..7 kHi | 24-31 rows+8..15 kHi
    uint32_t aOff = smemB + (uint32_t)((wM * 64 + (lane & 15)) * 80 + (lane >> 4) * 16);
    // B: lanes 0-7 n+0..7 kLo | 8-15 n+0..7 kHi | 16-23 n+8..15 kLo | 24-31 n+8..15 kHi
    uint32_t bOff = smemB + 20480u
                  + (uint32_t)((wN * 32 + (lane & 7) + ((lane >> 4) << 3)) * 80
                               + ((lane >> 3) & 1) * 16);

    float c[4][4][4];
    #pragma unroll
    for (int i = 0; i < 4; i++)
        #pragma unroll
        for (int j = 0; j < 4; j++)
            #pragma unroll
            for (int e = 0; e < 4; e++) c[i][j][e] = 0.f;

    int KIT = K / 32;
    gemm_load(gsm, Ab, Wb, K, 0, tid);
    gemm_load(gsm + GSTG_W, Ab, Wb, K, 1, tid);

    for (int kt = 0; kt < KIT; kt++) {
        asm volatile("cp.async.wait_group 1;");
        __syncthreads();
        if (kt + 2 < KIT) gemm_load(gsm + ((kt + 2) % 3) * GSTG_W, Ab, Wb, K, kt + 2, tid);
        else cpcommit();
        uint32_t sb = (uint32_t)((kt % 3) * GSTG_B);
        #pragma unroll
        for (int ch = 0; ch < 2; ch++) {
            uint32_t a[4][4], bb[2][4];
            #pragma unroll
            for (int mt = 0; mt < 4; mt++)
                ldsm4(a[mt], aOff + sb + (uint32_t)(mt * 1280 + ch * 32));
            #pragma unroll
            for (int ntp = 0; ntp < 2; ntp++)
                ldsm4(bb[ntp], bOff + sb + (uint32_t)(ntp * 1280 + ch * 32));
            #pragma unroll
            for (int mt = 0; mt < 4; mt++)
                #pragma unroll
                for (int nt = 0; nt < 4; nt++) {
                    uint32_t b[2] = { bb[nt >> 1][(nt & 1) * 2],
                                      bb[nt >> 1][(nt & 1) * 2 + 1] };
                    mma16(c[mt][nt], a[mt], b);
                }
        }
        // no bottom sync: 3-stage ring + wait_group 1 keeps writers/readers disjoint
    }

    size_t row0 = (size_t)blockIdx.y * 256;
    int col0 = blockIdx.x * 128 + wN * 32;
    #pragma unroll
    for (int mt = 0; mt < 4; mt++)
        #pragma unroll
        for (int nt = 0; nt < 4; nt++)
            #pragma unroll
            for (int ep = 0; ep < 2; ep++) {
                size_t row = row0 + wM * 64 + mt * 16 + g + ep * 8;
                int col = col0 + nt * 8 + 2 * tg;
                float vx = c[mt][nt][2 * ep]     + bias[col];
                float vy = c[mt][nt][2 * ep + 1] + bias[col + 1];
                *(__half2*)&C[row * G3H_ + col] = __floats2half2_rn(vx, vy);
            }
}

// ---------------- persistent recurrence: 128 CTAs x 8 cols, 16 warps (8M x 2K) ----------------
__global__ __launch_bounds__(THR, 1) void k_rec_persist(
    const float* __restrict__ W,      // whh raw fp32 [3072][1024]
    const __half* __restrict__ gx,    // [B][T][3H] fp16
    const float* __restrict__ bhh,    // [3H]
    __half* __restrict__ hbuf,        // [2][B*H] ping-pong fp16
    __half* __restrict__ yout,        // [B][T][H] fp16 or nullptr
    float* __restrict__ outf,         // [B][H] final hidden fp32
    unsigned* __restrict__ flags) {
    extern __shared__ char smc[];
    uint32_t* Wp  = (uint32_t*)(smc + WP_OFF);
    __half*   hds = (__half*)(smc + HOLD_OFF);
    float*    bhs = (float*)(smc + BIAS_OFF);
    float*    scr = (float*)(smc + SCR_OFF);

    int tid = threadIdx.x;
    int lane = tid & 31, wid = tid >> 5;
    int g = lane >> 2, tg = lane & 3;
    int wM = wid & 7;                  // batch slice (16 rows)
    int kh = wid >> 3;                 // K half
    int bid = blockIdx.x;
    int nb = bid * COLS;

    // pack resident weights: entry e = (k16*3+gt)*32+lane -> 2 words
    for (int e = tid; e < 6144; e += THR) {
        int lane_ = e & 31;
        int r = e >> 5;
        int gt = r % 3;
        int k16 = r / 3;
        int n = gt * H_ + nb + (lane_ >> 2);
        int k = k16 * 16 + 2 * (lane_ & 3);
        const float* wr = W + (size_t)n * H_;
        __half2 w0 = __floats2half2_rn(wr[k],     wr[k + 1]);
        __half2 w1 = __floats2half2_rn(wr[k + 8], wr[k + 9]);
        Wp[e * 2]     = *(uint32_t*)&w0;
        Wp[e * 2 + 1] = *(uint32_t*)&w1;
    }
    if (tid < 24) bhs[tid] = bhh[(tid >> 3) * H_ + nb + (tid & 7)];
    ((uint32_t*)hds)[tid] = 0u;    // persistent holds = h(0) = 0 (512 words)
    __syncthreads();

    char* myA = smc + AS_OFF + wid * AWARP;
    uint32_t aLdsm = (uint32_t)__cvta_generic_to_shared(myA)
                   + (uint32_t)(lane & 15) * 144 + (uint32_t)(lane >> 4) * 16;

    // per-thread stage-load map: 4 chunks of 16B (16 rows x 128B per stage)
    int srcOff[4]; int dstOff[4];
    #pragma unroll
    for (int i = 0; i < 4; i++) {
        int ch = lane + 32 * i;
        int r = ch >> 3, cc = ch & 7;
        srcOff[i] = r * H_ + kh * 512 + cc * 8;     // fp16 elements
        dstOff[i] = r * 144 + cc * 16;              // bytes within stage
    }

    // gx tile: 128 rows x 3 chunks (16B = 8 fp16 = one gate's 8 cols)
    // preload gx(0) into buffer 0 (kh==1 threads only; own commit group)
    if (kh == 1) {
        #pragma unroll
        for (int i = 0; i < 2; i++) {
            int idx = (tid - 256) + 256 * i;
            if (idx < 384) {
                int row = idx / 3, part = idx % 3;
                cp16(smc + GX_OFF + row * GX_ROWB + part * 16,
                     gx + (size_t)row * (T_ * G3H_) + (size_t)part * H_ + nb);
            }
        }
        cpcommit();
    }

    for (int t = 0; t < T_; t++) {
        const __half* hin = hbuf + (size_t)(t & 1) * (B_ * H_);
        __half* hout = hbuf + (size_t)((t + 1) & 1) * (B_ * H_);
        const __half* hwarp = hin + (size_t)(wM * 16) * H_;
        const __half* gxs = (const __half*)(smc + GX_OFF + (t & 1) * GX_BUF);

        float c[3][4];
        #pragma unroll
        for (int j = 0; j < 3; j++)
            #pragma unroll
            for (int e = 0; e < 4; e++) c[j][e] = 0.f;

        // stages 0,1 (one group each)
        #pragma unroll
        for (int s = 0; s < 2; s++) {
            char* dst = myA + s * ASTG;
            const __half* hsrc = hwarp + s * 64;
            #pragma unroll
            for (int i = 0; i < 4; i++)
                cp16(dst + dstOff[i], hsrc + srcOff[i]);
            cpcommit();
        }

        for (int kt = 0; kt < NKT; kt++) {
            asm volatile("cp.async.wait_group 1;");
            if (kt + 2 < NKT) {
                char* dst = myA + ((kt + 2) % 3) * ASTG;
                const __half* hsrc = hwarp + (kt + 2) * 64;
                #pragma unroll
                for (int i = 0; i < 4; i++)
                    cp16(dst + dstOff[i], hsrc + srcOff[i]);
            }
            cpcommit();

            uint32_t stAddr = aLdsm + (uint32_t)((kt % 3) * ASTG);
            #pragma unroll
            for (int c16 = 0; c16 < 4; c16++) {
                uint32_t a[4];
                ldsm4(a, stAddr + (uint32_t)c16 * 32);
                int k16 = kh * 32 + kt * 4 + c16;
                #pragma unroll
                for (int gt = 0; gt < 3; gt++) {
                    uint2 bv = *(const uint2*)&Wp[((k16 * 3 + gt) * 32 + lane) * 2];
                    uint32_t b[2] = { bv.x, bv.y };
                    mma16(c[gt], a, b);
                }
            }
        }

        // drain; kh==1 writes partials + prefetches gx(t+1); one bar; kh==0 epilogue
        asm volatile("cp.async.wait_group 0;");
        if (kh == 1) {
            float4* s = (float4*)(scr + ((size_t)(wid - 8) * 32 + lane) * 12);
            s[0] = make_float4(c[0][0], c[0][1], c[0][2], c[0][3]);
            s[1] = make_float4(c[1][0], c[1][1], c[1][2], c[1][3]);
            s[2] = make_float4(c[2][0], c[2][1], c[2][2], c[2][3]);
            if (t + 1 < T_) {
                char* gdst = smc + GX_OFF + ((t + 1) & 1) * GX_BUF;
                #pragma unroll
                for (int i = 0; i < 2; i++) {
                    int idx = (tid - 256) + 256 * i;
                    if (idx < 384) {
                        int row = idx / 3, part = idx % 3;
                        cp16(gdst + row * GX_ROWB + part * 16,
                             gx + (size_t)row * (T_ * G3H_) + (size_t)(t + 1) * G3H_
                                + (size_t)part * H_ + nb);
                    }
                }
                cpcommit();
            }
        }
        __syncthreads();

        if (kh == 0) {
            const float4* s = (const float4*)(scr + ((size_t)wid * 32 + lane) * 12);
            float4 p0 = s[0], p1 = s[1], p2 = s[2];
            c[0][0] += p0.x; c[0][1] += p0.y; c[0][2] += p0.z; c[0][3] += p0.w;
            c[1][0] += p1.x; c[1][1] += p1.y; c[1][2] += p1.z; c[1][3] += p1.w;
            c[2][0] += p2.x; c[2][1] += p2.y; c[2][2] += p2.z; c[2][3] += p2.w;

            #pragma unroll
            for (int ep = 0; ep < 2; ep++) {
                int row = wM * 16 + g + ep * 8;
                const __half* gxr = gxs + row * 32;      // 32 halves per row (24 + pad)
                __half* hrow_s = hds + row * 8;
                float2 hv;
                #pragma unroll
                for (int hf = 0; hf < 2; hf++) {
                    int e = 2 * ep + hf;
                    int lc = 2 * tg + hf;
                    float xr = __half2float(gxr[lc]);
                    float xz = __half2float(gxr[8 + lc]);
                    float xn = __half2float(gxr[16 + lc]);
                    float hr = c[0][e] + bhs[lc];
                    float hz = c[1][e] + bhs[8 + lc];
                    float hn = c[2][e] + bhs[16 + lc];
                    float rr = sigm_ap(xr + hr);
                    float zz = sigm_ap(xz + hz);
                    float nn = tanh_ap(xn + rr * hn);
                    float ho = __half2float(hrow_s[lc]);
                    float hnew = (1.f - zz) * nn + zz * ho;
                    (hf ? hv.y : hv.x) = hnew;
                }
                int col = nb + 2 * tg;
                __half2 hq = __floats2half2_rn(hv.x, hv.y);
                *(__half2*)&hrow_s[2 * tg] = hq;                 // persistent h_old
                *(__half2*)&hout[(size_t)row * H_ + col] = hq;
                if (yout)
                    *(__half2*)&yout[(size_t)row * (T_ * H_) + (size_t)t * H_ + col] = hq;
                if (t == T_ - 1) *(float2*)&outf[(size_t)row * H_ + col] = hv;
            }
        }

        if (t + 1 < T_) flag_barrier(flags, bid, tid, (unsigned)(t + 1));
    }
}

// ---------------- launch ----------------
extern "C" void kernel_launch(void* const* d_in, const int* in_sizes, int n_in,
                              void* d_out, int out_size) {
    const int*   src  = (const int*)d_in[0];
    const float* emb  = (const float*)d_in[1];
    const float* wih0 = (const float*)d_in[2];
    const float* whh0 = (const float*)d_in[3];
    const float* bih0 = (const float*)d_in[4];
    const float* bhh0 = (const float*)d_in[5];
    const float* wih1 = (const float*)d_in[6];
    const float* whh1 = (const float*)d_in[7];
    const float* bih1 = (const float*)d_in[8];
    const float* bhh1 = (const float*)d_in[9];
    float* out = (float*)d_out;

    __half *x0, *y0, *gx0, *gx1, *pwih0, *pwih1, *h0, *h1;
    unsigned *fl0, *fl1;
    cudaGetSymbolAddress((void**)&x0,    g_x0);
    cudaGetSymbolAddress((void**)&y0,    g_y0);
    cudaGetSymbolAddress((void**)&gx0,   g_gx0);
    cudaGetSymbolAddress((void**)&gx1,   g_gx1);
    cudaGetSymbolAddress((void**)&pwih0, g_wih0);
    cudaGetSymbolAddress((void**)&pwih1, g_wih1);
    cudaGetSymbolAddress((void**)&h0,    g_h0);
    cudaGetSymbolAddress((void**)&h1,    g_h1);
    cudaGetSymbolAddress((void**)&fl0,   g_flags0);
    cudaGetSymbolAddress((void**)&fl1,   g_flags1);

    cudaFuncSetAttribute(k_rec_persist, cudaFuncAttributeMaxDynamicSharedMemorySize, REC_SMEM);
    cudaFuncSetAttribute(k_gemm, cudaFuncAttributeMaxDynamicSharedMemorySize, GEMM_SMEM);

    // launch order keeps k_rec_persist at my-launch-index 3 for the ncu -s 5 window
    k_setup<<<2048, 256>>>(wih0, wih1);                                   // 0
    k_gather<<<NROW, 128>>>(src, emb, x0);                                // 1
    k_gemm<<<dim3(24, 256), 512, GEMM_SMEM>>>(x0, pwih0, bih0, gx0, E_);  // 2
    k_rec_persist<<<NCTA, THR, REC_SMEM>>>(whh0, gx0, bhh0, h0, y0, out, fl0);        // 3
    k_gemm<<<dim3(24, 256), 512, GEMM_SMEM>>>(y0, pwih1, bih1, gx1, H_);  // 4
    k_rec_persist<<<NCTA, THR, REC_SMEM>>>(whh1, gx1, bhh1, h1, nullptr, out + B_ * H_, fl1); // 5
}